// round 1
// baseline (speedup 1.0000x reference)
#include <cuda_runtime.h>
#include <cstdint>

// CoordsToNRF: out[b, p] = atoms_flat[p] * (AU2KCALMOLA / MAX_NRF) / ||c_i - c_j||^2
// where (i, j) enumerates the strict lower triangle of 128 atoms, row-major
// (i ascending, j < i ascending): p = i*(i-1)/2 + j.
//
// B = 2048, N_ATOMS = 128, NC2 = 8128. Output 2048*8128 floats (~66.6 MB):
// DRAM-write bound.

#define N_ATOMS 128
#define NC2     8128            // 128*127/2
#define NC2_V4  (NC2 / 4)       // 2032 float4 groups
#define BLOCK_THREADS 256

// AU2KCALMOLA / MAX_NRF = 627.5095 * 0.529177 / 100.0 (computed in double,
// rounded to float — well within the 1e-3 rel-err budget)
__device__ __forceinline__ float nrf_scale() {
    return (float)(627.5095 * 0.529177 / 100.0);
}

__global__ __launch_bounds__(BLOCK_THREADS)
void coords_to_nrf_kernel(const float* __restrict__ coords,
                          const float* __restrict__ atoms_flat,
                          float* __restrict__ out) {
    __shared__ float sc[N_ATOMS * 3];   // this batch's coords, [atom*3 + dim]

    const int b = blockIdx.x;
    const float* cb = coords + (size_t)b * (N_ATOMS * 3);

    // Stage coords for this batch into shared memory (384 floats).
    for (int t = threadIdx.x; t < N_ATOMS * 3; t += BLOCK_THREADS) {
        sc[t] = cb[t];
    }
    __syncthreads();

    float* ob = out + (size_t)b * NC2;
    const float scale = nrf_scale();

    // Each thread produces float4 groups of consecutive pairs -> STG.128.
    for (int g = threadIdx.x; g < NC2_V4; g += BLOCK_THREADS) {
        const int p0 = g * 4;
        float4 res;
        float* resf = reinterpret_cast<float*>(&res);

        #pragma unroll
        for (int k = 0; k < 4; k++) {
            const int p = p0 + k;
            // Decode p -> (i, j): i = floor((1 + sqrt(1 + 8p)) / 2), j = p - i(i-1)/2.
            // sqrtf rounding can be off by one row at boundaries; fix up.
            float f = sqrtf(8.0f * (float)p + 1.0f);
            int i = (int)((f + 1.0f) * 0.5f);
            int j = p - (i * (i - 1)) / 2;
            if (j < 0)       { i -= 1; j = p - (i * (i - 1)) / 2; }
            else if (j >= i) { i += 1; j = p - (i * (i - 1)) / 2; }

            const float dx = sc[i * 3 + 0] - sc[j * 3 + 0];
            const float dy = sc[i * 3 + 1] - sc[j * 3 + 1];
            const float dz = sc[i * 3 + 2] - sc[j * 3 + 2];
            const float d2 = dx * dx + dy * dy + dz * dz;

            // reference: r = sqrt(d2); 1/(r*r) == 1/d2 to ~1 ulp in fp32
            resf[k] = __ldg(&atoms_flat[p]) * scale / d2;
        }

        reinterpret_cast<float4*>(ob)[g] = res;
    }
}

extern "C" void kernel_launch(void* const* d_in, const int* in_sizes, int n_in,
                              void* d_out, int out_size) {
    const float* coords     = (const float*)d_in[0];  // [2048, 128, 3] f32
    const float* atoms_flat = (const float*)d_in[1];  // [8128] f32
    float* out = (float*)d_out;                       // [2048, 8128] f32

    const int batch = in_sizes[0] / (N_ATOMS * 3);    // 2048
    coords_to_nrf_kernel<<<batch, BLOCK_THREADS>>>(coords, atoms_flat, out);
}

// round 2
// speedup vs baseline: 1.2586x; 1.2586x over previous
#include <cuda_runtime.h>
#include <cstdint>

// CoordsToNRF: out[b, p] = atoms_flat[p] * (AU2KCALMOLA / MAX_NRF) / ||c_i - c_j||^2
// p enumerates strict lower triangle of 128 atoms row-major: p = i*(i-1)/2 + j.
// B = 2048, NC2 = 8128.
//
// Round-2 structure: block = (256 consecutive pairs) x (16 batches).
// Pair decode + atoms_flat load amortized over 16 batches; coords staged as
// float4-padded smem so each pair body is 2x LDS.128 + a handful of FP ops.

#define N_ATOMS 128
#define NC2     8128
#define NB      16          // batches per block
#define PCHUNK  256         // pairs per block (= blockDim.x)
#define NCHUNKS ((NC2 + PCHUNK - 1) / PCHUNK)   // 32

__device__ __forceinline__ float nrf_scale() {
    return (float)(627.5095 * 0.529177 / 100.0);
}

__global__ __launch_bounds__(PCHUNK)
void coords_to_nrf_kernel(const float* __restrict__ coords,
                          const float* __restrict__ atoms_flat,
                          float* __restrict__ out) {
    // Coords for NB batches, one float4 per atom (w unused): 16*128*16B = 32KB.
    __shared__ float4 sc[NB * N_ATOMS];

    const int pc = blockIdx.x;   // pair chunk  [0, 32)
    const int bg = blockIdx.y;   // batch group [0, 2048/NB)
    const int t  = threadIdx.x;

    // ---- Stage NB batches' coords into padded smem ----
    // gmem layout: [batch][atom][3] floats, contiguous across the NB batches.
    const float* cb = coords + (size_t)bg * NB * (N_ATOMS * 3);
    float* scf = reinterpret_cast<float*>(sc);
    #pragma unroll
    for (int idx = t; idx < NB * N_ATOMS * 3; idx += PCHUNK) {
        const int ba  = idx / 3;    // [batch*128 + atom]
        const int dim = idx - ba * 3;
        scf[ba * 4 + dim] = cb[idx];
    }
    __syncthreads();

    // ---- Decode this thread's pair once ----
    const int p = pc * PCHUNK + t;
    const bool valid = (p < NC2);
    const int pp = valid ? p : 0;

    float f = sqrtf(8.0f * (float)pp + 1.0f);
    int i = (int)((f + 1.0f) * 0.5f);
    int j = pp - (i * (i - 1)) / 2;
    if (j < 0)       { i -= 1; j = pp - (i * (i - 1)) / 2; }
    else if (j >= i) { i += 1; j = pp - (i * (i - 1)) / 2; }

    const float a_scaled = __ldg(&atoms_flat[pp]) * nrf_scale();

    float* ob = out + (size_t)bg * NB * NC2 + p;

    // ---- NB batches with the same (i, j): 2 LDS.128 + FP per element ----
    #pragma unroll
    for (int bb = 0; bb < NB; bb++) {
        const float4 ci = sc[bb * N_ATOMS + i];
        const float4 cj = sc[bb * N_ATOMS + j];
        const float dx = ci.x - cj.x;
        const float dy = ci.y - cj.y;
        const float dz = ci.z - cj.z;
        const float d2 = dx * dx + dy * dy + dz * dz;
        if (valid) {
            ob[(size_t)bb * NC2] = __fdividef(a_scaled, d2);  // MUFU.RCP + FMUL
        }
    }
}

extern "C" void kernel_launch(void* const* d_in, const int* in_sizes, int n_in,
                              void* d_out, int out_size) {
    const float* coords     = (const float*)d_in[0];  // [2048, 128, 3] f32
    const float* atoms_flat = (const float*)d_in[1];  // [8128] f32
    float* out = (float*)d_out;                       // [2048, 8128] f32

    const int batch = in_sizes[0] / (N_ATOMS * 3);    // 2048
    dim3 grid(NCHUNKS, batch / NB);                   // 32 x 128
    coords_to_nrf_kernel<<<grid, PCHUNK>>>(coords, atoms_flat, out);
}